// round 10
// baseline (speedup 1.0000x reference)
#include <cuda_runtime.h>

#define NN 10000
#define NE 320000
#define DH 256
#define NC 40

// Static scratch (allowed).
__device__ __align__(16) float4 g_bufA[NN * DH / 4];
__device__ __align__(16) float4 g_bufB[NN * DH / 4];
__device__ int g_idx[2 * NE];      // [0,NE)=src, [NE,2NE)=dst (clean int32)
__device__ int g_deg[NN];
__device__ int g_off[NN + 1];
__device__ int g_cur[NN];
__device__ int g_esrc[NE];         // src ids grouped by dst (CSR payload)
__device__ int g_is64;

// ---------------------------------------------------------------------------
// Detect edge-index dtype (int64 vs int32) AND zero the degree histogram.
// ---------------------------------------------------------------------------
__global__ void detect_and_zero(const int* __restrict__ p)
{
    const int i = blockIdx.x * blockDim.x + threadIdx.x;
    if (i < NN) g_deg[i] = 0;
    if (i == 0) {
        int any_nonzero = 0;
        for (int k = 0; k < 64; k++)
            any_nonzero |= p[2 * k + 1];
        g_is64 = (any_nonzero == 0) ? 1 : 0;
    }
}

// Convert edge index to clean int32 (clamped) AND histogram dst inline.
__global__ void convert_hist(const void* __restrict__ p)
{
    const int i = blockIdx.x * blockDim.x + threadIdx.x;
    if (i >= 2 * NE) return;
    int v;
    if (g_is64) v = (int)((const long long*)p)[i];
    else        v = ((const int*)p)[i];
    v = min(max(v, 0), NN - 1);
    g_idx[i] = v;
    if (i >= NE) atomicAdd(&g_deg[v], 1);
}

// ---------------------------------------------------------------------------
// Single-block exclusive scan: 1024 threads x 10 elements each.
// ---------------------------------------------------------------------------
__global__ void scan_deg_fast()
{
    const int t = threadIdx.x;
    const int lane = t & 31, warp = t >> 5;
    const int base = t * 10;

    int lexcl[10];
    int sum = 0;
#pragma unroll
    for (int i = 0; i < 10; i++) {
        const int idx = base + i;
        const int v = (idx < NN) ? __ldg(&g_deg[idx]) : 0;
        lexcl[i] = sum;
        sum += v;
    }

    int x = sum;
#pragma unroll
    for (int d = 1; d < 32; d <<= 1) {
        int y = __shfl_up_sync(0xffffffffu, x, d);
        if (lane >= d) x += y;
    }
    __shared__ int wsum[32];
    if (lane == 31) wsum[warp] = x;
    __syncthreads();
    if (warp == 0) {
        int w = wsum[lane];
#pragma unroll
        for (int d = 1; d < 32; d <<= 1) {
            int y = __shfl_up_sync(0xffffffffu, w, d);
            if (lane >= d) w += y;
        }
        wsum[lane] = w;
    }
    __syncthreads();

    const int texcl = (x - sum) + (warp ? wsum[warp - 1] : 0);
#pragma unroll
    for (int i = 0; i < 10; i++) {
        const int idx = base + i;
        if (idx < NN) {
            const int o = texcl + lexcl[i];
            g_off[idx] = o;
            g_cur[idx] = o;
        }
    }
    if (t == 1023) g_off[NN] = wsum[31];
}

__global__ void fill_csr()
{
    const int e = blockIdx.x * blockDim.x + threadIdx.x;
    if (e >= NE) return;
    const int dst = g_idx[NE + e];
    const int pos = atomicAdd(&g_cur[dst], 1);
    g_esrc[pos] = g_idx[e];
}

// ---------------------------------------------------------------------------
// 128x128 tiled SGEMM for N=K=256: C = act(A) @ B + bias.
// 256 threads, 8x8 microtile, BK=16, register-prefetch pipeline.
// ---------------------------------------------------------------------------
template<bool RELU_IN>
__global__ void __launch_bounds__(256, 2)
gemm128(const float* __restrict__ A, const float* __restrict__ B,
        const float* __restrict__ bias, float* __restrict__ C, int M)
{
    constexpr int KD = 256;   // K
    constexpr int ND = 256;   // N
    __shared__ float As[16][132];   // [k][m] transposed, padded stride
    __shared__ float Bs[16][128];   // [k][n]

    const int tid = threadIdx.x;
    const int ty = tid >> 4, tx = tid & 15;
    const int m0 = blockIdx.y * 128;
    const int n0 = blockIdx.x * 128;

    // Global-load assignments (2 float4 each for A and B per tile)
    const int a_row0 = (tid + 0)   >> 2, a_c40 = (tid + 0)   & 3;
    const int a_row1 = (tid + 256) >> 2, a_c41 = (tid + 256) & 3;
    const int b_row0 = (tid + 0)   >> 5, b_c40 = (tid + 0)   & 31;
    const int b_row1 = (tid + 256) >> 5, b_c41 = (tid + 256) & 31;

    float acc[8][8];
#pragma unroll
    for (int i = 0; i < 8; i++)
#pragma unroll
        for (int j = 0; j < 8; j++) acc[i][j] = 0.f;

    const float4 z4 = make_float4(0.f, 0.f, 0.f, 0.f);
    float4 ra0 = z4, ra1 = z4, rb0, rb1;

    // prefetch tile 0
    if (m0 + a_row0 < M)
        ra0 = *reinterpret_cast<const float4*>(&A[(size_t)(m0 + a_row0) * KD + a_c40 * 4]);
    if (m0 + a_row1 < M)
        ra1 = *reinterpret_cast<const float4*>(&A[(size_t)(m0 + a_row1) * KD + a_c41 * 4]);
    rb0 = *reinterpret_cast<const float4*>(&B[(size_t)b_row0 * ND + n0 + b_c40 * 4]);
    rb1 = *reinterpret_cast<const float4*>(&B[(size_t)b_row1 * ND + n0 + b_c41 * 4]);

    for (int k0 = 0; k0 < KD; k0 += 16) {
        float4 sa0 = ra0, sa1 = ra1;
        if (RELU_IN) {
            sa0.x = fmaxf(sa0.x, 0.f); sa0.y = fmaxf(sa0.y, 0.f);
            sa0.z = fmaxf(sa0.z, 0.f); sa0.w = fmaxf(sa0.w, 0.f);
            sa1.x = fmaxf(sa1.x, 0.f); sa1.y = fmaxf(sa1.y, 0.f);
            sa1.z = fmaxf(sa1.z, 0.f); sa1.w = fmaxf(sa1.w, 0.f);
        }
        As[a_c40 * 4 + 0][a_row0] = sa0.x; As[a_c40 * 4 + 1][a_row0] = sa0.y;
        As[a_c40 * 4 + 2][a_row0] = sa0.z; As[a_c40 * 4 + 3][a_row0] = sa0.w;
        As[a_c41 * 4 + 0][a_row1] = sa1.x; As[a_c41 * 4 + 1][a_row1] = sa1.y;
        As[a_c41 * 4 + 2][a_row1] = sa1.z; As[a_c41 * 4 + 3][a_row1] = sa1.w;
        *reinterpret_cast<float4*>(&Bs[b_row0][b_c40 * 4]) = rb0;
        *reinterpret_cast<float4*>(&Bs[b_row1][b_c41 * 4]) = rb1;
        __syncthreads();

        // prefetch next tile
        if (k0 + 16 < KD) {
            const int kn = k0 + 16;
            ra0 = z4; ra1 = z4;
            if (m0 + a_row0 < M)
                ra0 = *reinterpret_cast<const float4*>(&A[(size_t)(m0 + a_row0) * KD + kn + a_c40 * 4]);
            if (m0 + a_row1 < M)
                ra1 = *reinterpret_cast<const float4*>(&A[(size_t)(m0 + a_row1) * KD + kn + a_c41 * 4]);
            rb0 = *reinterpret_cast<const float4*>(&B[(size_t)(kn + b_row0) * ND + n0 + b_c40 * 4]);
            rb1 = *reinterpret_cast<const float4*>(&B[(size_t)(kn + b_row1) * ND + n0 + b_c41 * 4]);
        }

#pragma unroll
        for (int k = 0; k < 16; k++) {
            const float4 a0 = *reinterpret_cast<const float4*>(&As[k][ty * 8]);
            const float4 a1 = *reinterpret_cast<const float4*>(&As[k][ty * 8 + 4]);
            const float4 b0 = *reinterpret_cast<const float4*>(&Bs[k][tx * 8]);
            const float4 b1 = *reinterpret_cast<const float4*>(&Bs[k][tx * 8 + 4]);
            const float a[8] = {a0.x, a0.y, a0.z, a0.w, a1.x, a1.y, a1.z, a1.w};
            const float b[8] = {b0.x, b0.y, b0.z, b0.w, b1.x, b1.y, b1.z, b1.w};
#pragma unroll
            for (int i = 0; i < 8; i++)
#pragma unroll
                for (int j = 0; j < 8; j++)
                    acc[i][j] += a[i] * b[j];
        }
        __syncthreads();
    }

    const float4 bi0 = *reinterpret_cast<const float4*>(&bias[n0 + tx * 8]);
    const float4 bi1 = *reinterpret_cast<const float4*>(&bias[n0 + tx * 8 + 4]);
#pragma unroll
    for (int i = 0; i < 8; i++) {
        const int row = m0 + ty * 8 + i;
        if (row >= M) continue;
        float4 o0 = make_float4(acc[i][0] + bi0.x, acc[i][1] + bi0.y,
                                acc[i][2] + bi0.z, acc[i][3] + bi0.w);
        float4 o1 = make_float4(acc[i][4] + bi1.x, acc[i][5] + bi1.y,
                                acc[i][6] + bi1.z, acc[i][7] + bi1.w);
        *reinterpret_cast<float4*>(&C[(size_t)row * ND + n0 + tx * 8]) = o0;
        *reinterpret_cast<float4*>(&C[(size_t)row * ND + n0 + tx * 8 + 4]) = o1;
    }
}

// ---------------------------------------------------------------------------
// Tiled SGEMM 64x64 (layer 3, N=40): C = act(A) @ B + bias.
// ---------------------------------------------------------------------------
template<bool RELU_IN>
__global__ void gemm64(const float* __restrict__ A, const float* __restrict__ B,
                       const float* __restrict__ bias, float* __restrict__ C,
                       int M, int N, int K)
{
    __shared__ float As[16][64];
    __shared__ float Bs[16][64];
    const int tid = threadIdx.x;
    const int ty = tid >> 4, tx = tid & 15;
    const int m0 = blockIdx.y * 64;
    const int n0 = blockIdx.x * 64;

    float acc[4][4];
#pragma unroll
    for (int i = 0; i < 4; i++)
#pragma unroll
        for (int j = 0; j < 4; j++) acc[i][j] = 0.f;

    const int la = tid * 4;
    const int ar = la >> 4, ac = la & 15;
    const int br = la >> 6, bc = la & 63;
    const int grow = m0 + ar;
    const int gcol = n0 + bc;

    float4 va = make_float4(0.f, 0.f, 0.f, 0.f);
    if (grow < M)
        va = *reinterpret_cast<const float4*>(&A[(size_t)grow * K + ac]);
    float4 vb = make_float4(0.f, 0.f, 0.f, 0.f);
    if (gcol < N)
        vb = *reinterpret_cast<const float4*>(&B[(size_t)br * N + gcol]);

    for (int k0 = 0; k0 < K; k0 += 16) {
        float4 sa = va;
        if (RELU_IN) {
            sa.x = fmaxf(sa.x, 0.f); sa.y = fmaxf(sa.y, 0.f);
            sa.z = fmaxf(sa.z, 0.f); sa.w = fmaxf(sa.w, 0.f);
        }
        As[ac + 0][ar] = sa.x; As[ac + 1][ar] = sa.y;
        As[ac + 2][ar] = sa.z; As[ac + 3][ar] = sa.w;
        Bs[br][bc + 0] = vb.x; Bs[br][bc + 1] = vb.y;
        Bs[br][bc + 2] = vb.z; Bs[br][bc + 3] = vb.w;
        __syncthreads();

        if (k0 + 16 < K) {
            va = make_float4(0.f, 0.f, 0.f, 0.f);
            if (grow < M)
                va = *reinterpret_cast<const float4*>(&A[(size_t)grow * K + k0 + 16 + ac]);
            vb = make_float4(0.f, 0.f, 0.f, 0.f);
            if (gcol < N)
                vb = *reinterpret_cast<const float4*>(&B[(size_t)(k0 + 16 + br) * N + gcol]);
        }

#pragma unroll
        for (int k = 0; k < 16; k++) {
            const float4 a4 = *reinterpret_cast<const float4*>(&As[k][ty * 4]);
            const float4 b4 = *reinterpret_cast<const float4*>(&Bs[k][tx * 4]);
            const float a[4] = {a4.x, a4.y, a4.z, a4.w};
            const float b[4] = {b4.x, b4.y, b4.z, b4.w};
#pragma unroll
            for (int i = 0; i < 4; i++)
#pragma unroll
                for (int j = 0; j < 4; j++)
                    acc[i][j] += a[i] * b[j];
        }
        __syncthreads();
    }

#pragma unroll
    for (int i = 0; i < 4; i++) {
        int row = m0 + ty * 4 + i;
        if (row >= M) continue;
#pragma unroll
        for (int j = 0; j < 4; j++) {
            int col = n0 + tx * 4 + j;
            if (col < N)
                C[(size_t)row * N + col] = acc[i][j] + bias[col];
        }
    }
}

// ---------------------------------------------------------------------------
// Pull-mode aggregation, D=256, vectorized. No atomics.
// ---------------------------------------------------------------------------
__global__ void agg256v(const float4* __restrict__ h4, float4* __restrict__ out4)
{
    const int tid = threadIdx.x;
    const int node = blockIdx.x * 4 + (tid >> 6);
    const int f4 = tid & 63;
    if (node >= NN) return;
    const int beg = g_off[node], end = g_off[node + 1];

    float4 acc = make_float4(0.f, 0.f, 0.f, 0.f);
    int e = beg;
    for (; e + 4 <= end; e += 4) {
        const int s0 = g_esrc[e + 0], s1 = g_esrc[e + 1];
        const int s2 = g_esrc[e + 2], s3 = g_esrc[e + 3];
        const float4 v0 = h4[(size_t)s0 * 64 + f4];
        const float4 v1 = h4[(size_t)s1 * 64 + f4];
        const float4 v2 = h4[(size_t)s2 * 64 + f4];
        const float4 v3 = h4[(size_t)s3 * 64 + f4];
        acc.x += (v0.x + v1.x) + (v2.x + v3.x);
        acc.y += (v0.y + v1.y) + (v2.y + v3.y);
        acc.z += (v0.z + v1.z) + (v2.z + v3.z);
        acc.w += (v0.w + v1.w) + (v2.w + v3.w);
    }
    for (; e < end; e++) {
        const float4 v = h4[(size_t)g_esrc[e] * 64 + f4];
        acc.x += v.x; acc.y += v.y; acc.z += v.z; acc.w += v.w;
    }
    out4[(size_t)node * 64 + f4] = acc;
}

// ---------------------------------------------------------------------------
// Pull-mode aggregation, D=40 (+ReLU).
// ---------------------------------------------------------------------------
__global__ void agg40_relu(const float* __restrict__ h, float* __restrict__ out)
{
    const int tid = threadIdx.x;
    const int node = blockIdx.x * 4 + (tid >> 6);
    const int f = tid & 63;
    if (node >= NN || f >= NC) return;
    const int beg = g_off[node], end = g_off[node + 1];

    float acc = 0.f;
    int e = beg;
    for (; e + 4 <= end; e += 4) {
        const int s0 = g_esrc[e + 0], s1 = g_esrc[e + 1];
        const int s2 = g_esrc[e + 2], s3 = g_esrc[e + 3];
        const float v0 = h[(size_t)s0 * NC + f];
        const float v1 = h[(size_t)s1 * NC + f];
        const float v2 = h[(size_t)s2 * NC + f];
        const float v3 = h[(size_t)s3 * NC + f];
        acc += (v0 + v1) + (v2 + v3);
    }
    for (; e < end; e++)
        acc += h[(size_t)g_esrc[e] * NC + f];
    out[(size_t)node * NC + f] = fmaxf(acc, 0.f);
}

// ---------------------------------------------------------------------------
extern "C" void kernel_launch(void* const* d_in, const int* in_sizes, int n_in,
                              void* d_out, int out_size)
{
    const float* x  = (const float*)d_in[0];
    const void*  ei = d_in[1];
    const float* W1 = (const float*)d_in[2];
    const float* b1 = (const float*)d_in[3];
    const float* W2 = (const float*)d_in[4];
    const float* b2 = (const float*)d_in[5];
    const float* W3 = (const float*)d_in[6];
    const float* b3 = (const float*)d_in[7];
    float* out = (float*)d_out;

    float4 *bufA, *bufB;
    cudaGetSymbolAddress((void**)&bufA, g_bufA);
    cudaGetSymbolAddress((void**)&bufB, g_bufB);

    static cudaStream_t s_side = nullptr;
    static cudaEvent_t ev_fork = nullptr, ev_join = nullptr;
    if (s_side == nullptr) {
        cudaStreamCreateWithFlags(&s_side, cudaStreamNonBlocking);
        cudaEventCreateWithFlags(&ev_fork, cudaEventDisableTiming);
        cudaEventCreateWithFlags(&ev_join, cudaEventDisableTiming);
    }

    const dim3 blk(256);
    const dim3 g128(DH / 128, (NN + 127) / 128);      // (2, 79)
    const dim3 gCls((NC + 63) / 64, (NN + 63) / 64);  // (1, 157)

    // Fork: CSR build on side stream, layer-1 GEMM on main stream.
    cudaEventRecord(ev_fork, 0);
    cudaStreamWaitEvent(s_side, ev_fork, 0);

    detect_and_zero<<<(NN + 255) / 256, blk, 0, s_side>>>((const int*)ei);
    convert_hist<<<(2 * NE + 255) / 256, blk, 0, s_side>>>(ei);
    scan_deg_fast<<<1, 1024, 0, s_side>>>();
    fill_csr<<<(NE + 255) / 256, blk, 0, s_side>>>();
    cudaEventRecord(ev_join, s_side);

    // Layer 1 GEMM overlaps the CSR build.
    gemm128<false><<<g128, blk>>>(x, W1, b1, (float*)bufB, NN);

    // Join: aggregation needs both GEMM1 output and the CSR.
    cudaStreamWaitEvent(0, ev_join, 0);
    agg256v<<<(NN + 3) / 4, blk>>>(bufB, bufA);

    // Layer 2
    gemm128<true><<<g128, blk>>>((const float*)bufA, W2, b2, (float*)bufB, NN);
    agg256v<<<(NN + 3) / 4, blk>>>(bufB, bufA);

    // Layer 3
    gemm64<true><<<gCls, blk>>>((const float*)bufA, W3, b3, (float*)bufB, NN, NC, DH);
    agg40_relu<<<(NN + 3) / 4, blk>>>((const float*)bufB, out);
}

// round 11
// speedup vs baseline: 1.1604x; 1.1604x over previous
#include <cuda_runtime.h>

#define NN 10000
#define NE 320000
#define DH 256
#define NC 40

// Static scratch (allowed).
__device__ __align__(16) float4 g_bufA[NN * DH / 4];
__device__ __align__(16) float4 g_bufB[NN * DH / 4];
__device__ int g_idx[2 * NE];      // [0,NE)=src, [NE,2NE)=dst (clean int32)
__device__ int g_deg[NN];
__device__ int g_off[NN + 1];
__device__ int g_cur[NN];
__device__ int g_esrc[NE];         // src ids grouped by dst (CSR payload)
__device__ int g_is64;

// ---------------------------------------------------------------------------
// Detect edge-index dtype (int64 vs int32) AND zero the degree histogram.
// ---------------------------------------------------------------------------
__global__ void detect_and_zero(const int* __restrict__ p)
{
    const int i = blockIdx.x * blockDim.x + threadIdx.x;
    if (i < NN) g_deg[i] = 0;
    if (i == 0) {
        int any_nonzero = 0;
        for (int k = 0; k < 64; k++)
            any_nonzero |= p[2 * k + 1];
        g_is64 = (any_nonzero == 0) ? 1 : 0;
    }
}

// Convert edge index to clean int32 (clamped) AND histogram dst inline.
__global__ void convert_hist(const void* __restrict__ p)
{
    const int i = blockIdx.x * blockDim.x + threadIdx.x;
    if (i >= 2 * NE) return;
    int v;
    if (g_is64) v = (int)((const long long*)p)[i];
    else        v = ((const int*)p)[i];
    v = min(max(v, 0), NN - 1);
    g_idx[i] = v;
    if (i >= NE) atomicAdd(&g_deg[v], 1);
}

// ---------------------------------------------------------------------------
// Single-block exclusive scan: 1024 threads x 10 elements each.
// ---------------------------------------------------------------------------
__global__ void scan_deg_fast()
{
    const int t = threadIdx.x;
    const int lane = t & 31, warp = t >> 5;
    const int base = t * 10;

    int lexcl[10];
    int sum = 0;
#pragma unroll
    for (int i = 0; i < 10; i++) {
        const int idx = base + i;
        const int v = (idx < NN) ? __ldg(&g_deg[idx]) : 0;
        lexcl[i] = sum;
        sum += v;
    }

    int x = sum;
#pragma unroll
    for (int d = 1; d < 32; d <<= 1) {
        int y = __shfl_up_sync(0xffffffffu, x, d);
        if (lane >= d) x += y;
    }
    __shared__ int wsum[32];
    if (lane == 31) wsum[warp] = x;
    __syncthreads();
    if (warp == 0) {
        int w = wsum[lane];
#pragma unroll
        for (int d = 1; d < 32; d <<= 1) {
            int y = __shfl_up_sync(0xffffffffu, w, d);
            if (lane >= d) w += y;
        }
        wsum[lane] = w;
    }
    __syncthreads();

    const int texcl = (x - sum) + (warp ? wsum[warp - 1] : 0);
#pragma unroll
    for (int i = 0; i < 10; i++) {
        const int idx = base + i;
        if (idx < NN) {
            const int o = texcl + lexcl[i];
            g_off[idx] = o;
            g_cur[idx] = o;
        }
    }
    if (t == 1023) g_off[NN] = wsum[31];
}

__global__ void fill_csr()
{
    const int e = blockIdx.x * blockDim.x + threadIdx.x;
    if (e >= NE) return;
    const int dst = g_idx[NE + e];
    const int pos = atomicAdd(&g_cur[dst], 1);
    g_esrc[pos] = g_idx[e];
}

// ---------------------------------------------------------------------------
// 128x64 tiled SGEMM for N=K=256: C = act(A) @ B + bias.
// 256 threads, 8x4 microtile, BK=16, register-prefetch pipeline.
// Grid (4, 79) = 316 blocks -> ~2.1 CTA/SM.
// ---------------------------------------------------------------------------
template<bool RELU_IN>
__global__ void gemm128x64(const float* __restrict__ A, const float* __restrict__ B,
                           const float* __restrict__ bias, float* __restrict__ C,
                           int M)
{
    constexpr int KD = 256;
    constexpr int ND = 256;
    __shared__ float As[16][132];   // [k][m] transposed, padded stride
    __shared__ float Bs[16][64];    // [k][n]

    const int tid = threadIdx.x;
    const int ty = tid >> 4, tx = tid & 15;
    const int m0 = blockIdx.y * 128;
    const int n0 = blockIdx.x * 64;

    // A: 128x16 tile = 512 float4 -> 2 per thread. B: 16x64 = 256 float4 -> 1.
    const int a_row0 = (tid + 0)   >> 2, a_c40 = (tid + 0)   & 3;
    const int a_row1 = (tid + 256) >> 2, a_c41 = (tid + 256) & 3;
    const int b_row  = tid >> 4,         b_c4  = tid & 15;

    float acc[8][4];
#pragma unroll
    for (int i = 0; i < 8; i++)
#pragma unroll
        for (int j = 0; j < 4; j++) acc[i][j] = 0.f;

    const float4 z4 = make_float4(0.f, 0.f, 0.f, 0.f);
    float4 ra0 = z4, ra1 = z4, rb;

    if (m0 + a_row0 < M)
        ra0 = *reinterpret_cast<const float4*>(&A[(size_t)(m0 + a_row0) * KD + a_c40 * 4]);
    if (m0 + a_row1 < M)
        ra1 = *reinterpret_cast<const float4*>(&A[(size_t)(m0 + a_row1) * KD + a_c41 * 4]);
    rb = *reinterpret_cast<const float4*>(&B[(size_t)b_row * ND + n0 + b_c4 * 4]);

    for (int k0 = 0; k0 < KD; k0 += 16) {
        float4 sa0 = ra0, sa1 = ra1;
        if (RELU_IN) {
            sa0.x = fmaxf(sa0.x, 0.f); sa0.y = fmaxf(sa0.y, 0.f);
            sa0.z = fmaxf(sa0.z, 0.f); sa0.w = fmaxf(sa0.w, 0.f);
            sa1.x = fmaxf(sa1.x, 0.f); sa1.y = fmaxf(sa1.y, 0.f);
            sa1.z = fmaxf(sa1.z, 0.f); sa1.w = fmaxf(sa1.w, 0.f);
        }
        As[a_c40 * 4 + 0][a_row0] = sa0.x; As[a_c40 * 4 + 1][a_row0] = sa0.y;
        As[a_c40 * 4 + 2][a_row0] = sa0.z; As[a_c40 * 4 + 3][a_row0] = sa0.w;
        As[a_c41 * 4 + 0][a_row1] = sa1.x; As[a_c41 * 4 + 1][a_row1] = sa1.y;
        As[a_c41 * 4 + 2][a_row1] = sa1.z; As[a_c41 * 4 + 3][a_row1] = sa1.w;
        *reinterpret_cast<float4*>(&Bs[b_row][b_c4 * 4]) = rb;
        __syncthreads();

        if (k0 + 16 < KD) {
            const int kn = k0 + 16;
            ra0 = z4; ra1 = z4;
            if (m0 + a_row0 < M)
                ra0 = *reinterpret_cast<const float4*>(&A[(size_t)(m0 + a_row0) * KD + kn + a_c40 * 4]);
            if (m0 + a_row1 < M)
                ra1 = *reinterpret_cast<const float4*>(&A[(size_t)(m0 + a_row1) * KD + kn + a_c41 * 4]);
            rb = *reinterpret_cast<const float4*>(&B[(size_t)(kn + b_row) * ND + n0 + b_c4 * 4]);
        }

#pragma unroll
        for (int k = 0; k < 16; k++) {
            const float4 a0 = *reinterpret_cast<const float4*>(&As[k][ty * 8]);
            const float4 a1 = *reinterpret_cast<const float4*>(&As[k][ty * 8 + 4]);
            const float4 b4 = *reinterpret_cast<const float4*>(&Bs[k][tx * 4]);
            const float a[8] = {a0.x, a0.y, a0.z, a0.w, a1.x, a1.y, a1.z, a1.w};
            const float b[4] = {b4.x, b4.y, b4.z, b4.w};
#pragma unroll
            for (int i = 0; i < 8; i++)
#pragma unroll
                for (int j = 0; j < 4; j++)
                    acc[i][j] += a[i] * b[j];
        }
        __syncthreads();
    }

    const float4 bi = *reinterpret_cast<const float4*>(&bias[n0 + tx * 4]);
#pragma unroll
    for (int i = 0; i < 8; i++) {
        const int row = m0 + ty * 8 + i;
        if (row >= M) continue;
        float4 o = make_float4(acc[i][0] + bi.x, acc[i][1] + bi.y,
                               acc[i][2] + bi.z, acc[i][3] + bi.w);
        *reinterpret_cast<float4*>(&C[(size_t)row * ND + n0 + tx * 4]) = o;
    }
}

// ---------------------------------------------------------------------------
// Tiled SGEMM 64x64 (layer 3, N=40): C = act(A) @ B + bias.
// ---------------------------------------------------------------------------
template<bool RELU_IN>
__global__ void gemm64(const float* __restrict__ A, const float* __restrict__ B,
                       const float* __restrict__ bias, float* __restrict__ C,
                       int M, int N, int K)
{
    __shared__ float As[16][64];
    __shared__ float Bs[16][64];
    const int tid = threadIdx.x;
    const int ty = tid >> 4, tx = tid & 15;
    const int m0 = blockIdx.y * 64;
    const int n0 = blockIdx.x * 64;

    float acc[4][4];
#pragma unroll
    for (int i = 0; i < 4; i++)
#pragma unroll
        for (int j = 0; j < 4; j++) acc[i][j] = 0.f;

    const int la = tid * 4;
    const int ar = la >> 4, ac = la & 15;
    const int br = la >> 6, bc = la & 63;
    const int grow = m0 + ar;
    const int gcol = n0 + bc;

    float4 va = make_float4(0.f, 0.f, 0.f, 0.f);
    if (grow < M)
        va = *reinterpret_cast<const float4*>(&A[(size_t)grow * K + ac]);
    float4 vb = make_float4(0.f, 0.f, 0.f, 0.f);
    if (gcol < N)
        vb = *reinterpret_cast<const float4*>(&B[(size_t)br * N + gcol]);

    for (int k0 = 0; k0 < K; k0 += 16) {
        float4 sa = va;
        if (RELU_IN) {
            sa.x = fmaxf(sa.x, 0.f); sa.y = fmaxf(sa.y, 0.f);
            sa.z = fmaxf(sa.z, 0.f); sa.w = fmaxf(sa.w, 0.f);
        }
        As[ac + 0][ar] = sa.x; As[ac + 1][ar] = sa.y;
        As[ac + 2][ar] = sa.z; As[ac + 3][ar] = sa.w;
        Bs[br][bc + 0] = vb.x; Bs[br][bc + 1] = vb.y;
        Bs[br][bc + 2] = vb.z; Bs[br][bc + 3] = vb.w;
        __syncthreads();

        if (k0 + 16 < K) {
            va = make_float4(0.f, 0.f, 0.f, 0.f);
            if (grow < M)
                va = *reinterpret_cast<const float4*>(&A[(size_t)grow * K + k0 + 16 + ac]);
            vb = make_float4(0.f, 0.f, 0.f, 0.f);
            if (gcol < N)
                vb = *reinterpret_cast<const float4*>(&B[(size_t)(k0 + 16 + br) * N + gcol]);
        }

#pragma unroll
        for (int k = 0; k < 16; k++) {
            const float4 a4 = *reinterpret_cast<const float4*>(&As[k][ty * 4]);
            const float4 b4 = *reinterpret_cast<const float4*>(&Bs[k][tx * 4]);
            const float a[4] = {a4.x, a4.y, a4.z, a4.w};
            const float b[4] = {b4.x, b4.y, b4.z, b4.w};
#pragma unroll
            for (int i = 0; i < 4; i++)
#pragma unroll
                for (int j = 0; j < 4; j++)
                    acc[i][j] += a[i] * b[j];
        }
        __syncthreads();
    }

#pragma unroll
    for (int i = 0; i < 4; i++) {
        int row = m0 + ty * 4 + i;
        if (row >= M) continue;
#pragma unroll
        for (int j = 0; j < 4; j++) {
            int col = n0 + tx * 4 + j;
            if (col < N)
                C[(size_t)row * N + col] = acc[i][j] + bias[col];
        }
    }
}

// ---------------------------------------------------------------------------
// Pull-mode aggregation, D=256, vectorized. No atomics.
// ---------------------------------------------------------------------------
__global__ void agg256v(const float4* __restrict__ h4, float4* __restrict__ out4)
{
    const int tid = threadIdx.x;
    const int node = blockIdx.x * 4 + (tid >> 6);
    const int f4 = tid & 63;
    if (node >= NN) return;
    const int beg = g_off[node], end = g_off[node + 1];

    float4 acc = make_float4(0.f, 0.f, 0.f, 0.f);
    int e = beg;
    for (; e + 4 <= end; e += 4) {
        const int s0 = g_esrc[e + 0], s1 = g_esrc[e + 1];
        const int s2 = g_esrc[e + 2], s3 = g_esrc[e + 3];
        const float4 v0 = h4[(size_t)s0 * 64 + f4];
        const float4 v1 = h4[(size_t)s1 * 64 + f4];
        const float4 v2 = h4[(size_t)s2 * 64 + f4];
        const float4 v3 = h4[(size_t)s3 * 64 + f4];
        acc.x += (v0.x + v1.x) + (v2.x + v3.x);
        acc.y += (v0.y + v1.y) + (v2.y + v3.y);
        acc.z += (v0.z + v1.z) + (v2.z + v3.z);
        acc.w += (v0.w + v1.w) + (v2.w + v3.w);
    }
    for (; e < end; e++) {
        const float4 v = h4[(size_t)g_esrc[e] * 64 + f4];
        acc.x += v.x; acc.y += v.y; acc.z += v.z; acc.w += v.w;
    }
    out4[(size_t)node * 64 + f4] = acc;
}

// ---------------------------------------------------------------------------
// Pull-mode aggregation, D=40 (+ReLU): 8 nodes per 320-thread block, no idle
// lanes.
// ---------------------------------------------------------------------------
__global__ void agg40_relu(const float* __restrict__ h, float* __restrict__ out)
{
    const int tid = threadIdx.x;
    const int node = blockIdx.x * 8 + tid / NC;
    const int f = tid % NC;
    if (node >= NN) return;
    const int beg = g_off[node], end = g_off[node + 1];

    float acc = 0.f;
    int e = beg;
    for (; e + 4 <= end; e += 4) {
        const int s0 = g_esrc[e + 0], s1 = g_esrc[e + 1];
        const int s2 = g_esrc[e + 2], s3 = g_esrc[e + 3];
        const float v0 = h[(size_t)s0 * NC + f];
        const float v1 = h[(size_t)s1 * NC + f];
        const float v2 = h[(size_t)s2 * NC + f];
        const float v3 = h[(size_t)s3 * NC + f];
        acc += (v0 + v1) + (v2 + v3);
    }
    for (; e < end; e++)
        acc += h[(size_t)g_esrc[e] * NC + f];
    out[(size_t)node * NC + f] = fmaxf(acc, 0.f);
}

// ---------------------------------------------------------------------------
extern "C" void kernel_launch(void* const* d_in, const int* in_sizes, int n_in,
                              void* d_out, int out_size)
{
    const float* x  = (const float*)d_in[0];
    const void*  ei = d_in[1];
    const float* W1 = (const float*)d_in[2];
    const float* b1 = (const float*)d_in[3];
    const float* W2 = (const float*)d_in[4];
    const float* b2 = (const float*)d_in[5];
    const float* W3 = (const float*)d_in[6];
    const float* b3 = (const float*)d_in[7];
    float* out = (float*)d_out;

    float4 *bufA, *bufB;
    cudaGetSymbolAddress((void**)&bufA, g_bufA);
    cudaGetSymbolAddress((void**)&bufB, g_bufB);

    static cudaStream_t s_side = nullptr;
    static cudaEvent_t ev_fork = nullptr, ev_join = nullptr;
    if (s_side == nullptr) {
        cudaStreamCreateWithFlags(&s_side, cudaStreamNonBlocking);
        cudaEventCreateWithFlags(&ev_fork, cudaEventDisableTiming);
        cudaEventCreateWithFlags(&ev_join, cudaEventDisableTiming);
    }

    const dim3 blk(256);
    const dim3 gHid(DH / 64, (NN + 127) / 128);       // (4, 79) = 316 blocks
    const dim3 gCls((NC + 63) / 64, (NN + 63) / 64);  // (1, 157)

    // Fork: CSR build on side stream, layer-1 GEMM on main stream.
    cudaEventRecord(ev_fork, 0);
    cudaStreamWaitEvent(s_side, ev_fork, 0);

    detect_and_zero<<<(NN + 255) / 256, blk, 0, s_side>>>((const int*)ei);
    convert_hist<<<(2 * NE + 255) / 256, blk, 0, s_side>>>(ei);
    scan_deg_fast<<<1, 1024, 0, s_side>>>();
    fill_csr<<<(NE + 255) / 256, blk, 0, s_side>>>();
    cudaEventRecord(ev_join, s_side);

    // Layer 1 GEMM overlaps the CSR build.
    gemm128x64<false><<<gHid, blk>>>(x, W1, b1, (float*)bufB, NN);

    // Join: aggregation needs both GEMM1 output and the CSR.
    cudaStreamWaitEvent(0, ev_join, 0);
    agg256v<<<(NN + 3) / 4, blk>>>(bufB, bufA);

    // Layer 2
    gemm128x64<true><<<gHid, blk>>>((const float*)bufA, W2, b2, (float*)bufB, NN);
    agg256v<<<(NN + 3) / 4, blk>>>(bufB, bufA);

    // Layer 3
    gemm64<true><<<gCls, blk>>>((const float*)bufA, W3, b3, (float*)bufB, NN, NC, DH);
    agg40_relu<<<(NN + 7) / 8, 320>>>((const float*)bufB, out);
}